// round 8
// baseline (speedup 1.0000x reference)
#include <cuda_runtime.h>
#include <cooperative_groups.h>
#include <math.h>
#include <stdint.h>

namespace cg = cooperative_groups;

#define T_STEPS 32768
#define DIM 256
#define G3 768            // 3*DIM
#define FFN_DIM 1024
#define TX_BYTES 1024     // per-step bytes into each CTA: NCC * (DIM/NCC) * 4B

// ---------------- scratch (static device allocations; no cudaMalloc allowed) ----
__device__ float g_xg[T_STEPS * G3];
__device__ float g_ys[T_STEPS * DIM];
__device__ float g_t3[T_STEPS * DIM];
__device__ float g_y [T_STEPS * DIM];
__device__ float g_t1[T_STEPS * FFN_DIM];
__device__ float g_t6[T_STEPS * DIM];

// ---------------- packed f32x2 helpers ------------------------------------------
__device__ __forceinline__ unsigned long long pack2(float lo, float hi) {
    unsigned long long r;
    asm("mov.b64 %0, {%1, %2};" : "=l"(r) : "f"(lo), "f"(hi));
    return r;
}
__device__ __forceinline__ unsigned long long dup2(float v) {
    unsigned long long r;
    asm("mov.b64 %0, {%1, %1};" : "=l"(r) : "f"(v));
    return r;
}
__device__ __forceinline__ void fma2(unsigned long long& acc,
                                     unsigned long long a, unsigned long long b) {
    asm("fma.rn.f32x2 %0, %1, %2, %0;" : "+l"(acc) : "l"(a), "l"(b));
}
__device__ __forceinline__ unsigned long long add2(unsigned long long a,
                                                   unsigned long long b) {
    unsigned long long r;
    asm("add.rn.f32x2 %0, %1, %2;" : "=l"(r) : "l"(a), "l"(b));
    return r;
}
__device__ __forceinline__ float hsum2(unsigned long long v) {
    float lo, hi;
    asm("mov.b64 {%0, %1}, %2;" : "=f"(lo), "=f"(hi) : "l"(v));
    return lo + hi;
}

// ---------------- fast transcendentals ------------------------------------------
__device__ __forceinline__ float sigmoid_fast(float x) {
    return __fdividef(1.f, 1.f + __expf(-x));
}
__device__ __forceinline__ float tanh_fast(float x) {
    float e = __expf(2.f * x);
    return 1.f - __fdividef(2.f, e + 1.f);
}

// ---------------- smem / cluster primitives --------------------------------------
__device__ __forceinline__ uint32_t smem_u32(const void* p) {
    uint32_t a;
    asm("{ .reg .u64 t; cvta.to.shared.u64 t, %1; cvt.u32.u64 %0, t; }"
        : "=r"(a) : "l"(p));
    return a;
}
__device__ __forceinline__ uint32_t mapa_u32(uint32_t laddr, uint32_t rank) {
    uint32_t r;
    asm("mapa.shared::cluster.u32 %0, %1, %2;" : "=r"(r) : "r"(laddr), "r"(rank));
    return r;
}
__device__ __forceinline__ void mbar_init(uint32_t mbar, uint32_t count) {
    asm volatile("mbarrier.init.shared.b64 [%0], %1;" :: "r"(mbar), "r"(count) : "memory");
}
__device__ __forceinline__ void mbar_arrive_expect_tx(uint32_t mbar, uint32_t bytes) {
    asm volatile("mbarrier.arrive.expect_tx.shared.b64 _, [%0], %1;"
                 :: "r"(mbar), "r"(bytes) : "memory");
}
__device__ __forceinline__ void mbar_wait_parity_acq(uint32_t mbar, uint32_t parity) {
    asm volatile(
        "{\n\t.reg .pred P;\n\t"
        "WL_%=:\n\t"
        "mbarrier.try_wait.parity.acquire.cluster.shared::cta.b64 P, [%0], %1, 0x989680;\n\t"
        "@P bra.uni WD_%=;\n\t"
        "bra.uni WL_%=;\n\t"
        "WD_%=:\n\t}"
        :: "r"(mbar), "r"(parity) : "memory");
}
__device__ __forceinline__ void st_async_b32(uint32_t raddr, float v, uint32_t rmbar) {
    asm volatile(
        "st.async.shared::cluster.mbarrier::complete_tx::bytes.b32 [%0], %1, [%2];"
        :: "r"(raddr), "f"(v), "r"(rmbar) : "memory");
}
__device__ __forceinline__ void cluster_arrive_rel() {
    asm volatile("barrier.cluster.arrive.aligned;" ::: "memory");
}
__device__ __forceinline__ void cluster_wait_acq() {
    asm volatile("barrier.cluster.wait.aligned;" ::: "memory");
}

// ================================================================================
// GRU scan, templated on cluster size NCC (16 preferred, 8 fallback).
// Thread (m, q) computes r/z/n partial dots for h-element m over k-chunk q
// (3 x 32 weights in regs as f32x2). Lanes are m*8+q, so the 8-thread reduce is
// intra-warp shfl and lane q==0 computes gates + st.async broadcast directly —
// no cross-warp exchange, no __syncthreads in the loop.
// ================================================================================
template <int NCC>
__global__ void __launch_bounds__(2048 / NCC, 1)
scan_kernel(const float* __restrict__ Wh, const float* __restrict__ bh,
            const float* __restrict__ h0)
{
    constexpr int M   = DIM / NCC;   // h elements per CTA (16 or 32)
    constexpr int NTH = M * 8;       // threads (128 or 256)

    cg::cluster_group cluster = cg::this_cluster();
    const unsigned crank = cluster.block_rank();

    __shared__ __align__(16) float h_s[2][DIM];
    __shared__ __align__(8) unsigned long long mbar[2];

    const int tid   = threadIdx.x;
    const int m_loc = tid >> 3;      // 0..M-1
    const int q     = tid & 7;       // k-chunk 0..7 (32 floats each)
    const int hbase = (int)crank * M;

    const uint32_t mbar0 = smem_u32(&mbar[0]);
    if (tid == 0) { mbar_init(mbar0, 1); mbar_init(mbar0 + 8, 1); }

    // ---- 96 weights/thread: 3 gates x 32 k (chunk q), rotated sub-chunk order ---
    unsigned long long w2[3][16];
#pragma unroll
    for (int j = 0; j < 8; ++j) {
        const int c = (j + q) & 7;
        const int k = q * 32 + c * 4;
#pragma unroll
        for (int g = 0; g < 3; ++g) {
            const int gcol = g * DIM + hbase + m_loc;
            w2[g][2 * j]     = pack2(Wh[(k + 0) * G3 + gcol], Wh[(k + 1) * G3 + gcol]);
            w2[g][2 * j + 1] = pack2(Wh[(k + 2) * G3 + gcol], Wh[(k + 3) * G3 + gcol]);
        }
    }
    float bcol[3];
#pragma unroll
    for (int g = 0; g < 3; ++g) bcol[g] = bh[g * DIM + hbase + m_loc];

    for (int i = tid; i < DIM; i += NTH) h_s[0][i] = h0[i];

    const bool is_gate = (q == 0);
    float xr = 0.f, xz = 0.f, xn = 0.f;
    uint32_t rdata[NCC], rmbar[NCC];
    if (is_gate) {
        const float* p = g_xg + hbase + m_loc;
        xr = p[0]; xz = p[DIM]; xn = p[2 * DIM];
        const uint32_t ldata = smem_u32(&h_s[0][hbase + m_loc]);
#pragma unroll
        for (int d = 0; d < NCC; ++d) {
            rdata[d] = mapa_u32(ldata, (uint32_t)d);
            rmbar[d] = mapa_u32(mbar0, (uint32_t)d);
        }
    }

    cluster.sync();   // mbarrier inits + h_s[0] visible cluster-wide

#pragma unroll 1
    for (int t = 0; t < T_STEPS; ++t) {
        const int b = t & 1;
        if (t > 0)
            mbar_wait_parity_acq(mbar0 + (uint32_t)(b * 8), (uint32_t)(((t - 1) >> 1) & 1));
        if (tid == 0 && t + 1 < T_STEPS)
            mbar_arrive_expect_tx(mbar0 + (uint32_t)(((t + 1) & 1) * 8), TX_BYTES);

        // ---- 3-gate partial dot over chunk q (rotation -> conflict-free LDS) ----
        const ulonglong2* hb = (const ulonglong2*)(h_s[b]) + q * 8;
        unsigned long long aA[3] = {0ull, 0ull, 0ull};
        unsigned long long aB[3] = {0ull, 0ull, 0ull};
#pragma unroll
        for (int j = 0; j < 8; ++j) {
            const ulonglong2 hv = hb[(j + q) & 7];
#pragma unroll
            for (int g = 0; g < 3; ++g) {
                fma2(aA[g], w2[g][2 * j], hv.x);
                fma2(aB[g], w2[g][2 * j + 1], hv.y);
            }
        }
        float s[3];
#pragma unroll
        for (int g = 0; g < 3; ++g) s[g] = hsum2(add2(aA[g], aB[g]));
        // reduce over the 8 q-lanes (stride 4,2,1), 3 gates interleaved
#pragma unroll
        for (int off = 4; off > 0; off >>= 1)
#pragma unroll
            for (int g = 0; g < 3; ++g)
                s[g] += __shfl_down_sync(0xffffffffu, s[g], off);

        // ---- gates + async broadcast (q==0 lanes only) ----
        if (is_gate) {
            const float r  = sigmoid_fast(xr + s[0] + bcol[0]);
            const float z  = sigmoid_fast(xz + s[1] + bcol[1]);
            const float hn = s[2] + bcol[2];
            const float nn = tanh_fast(xn + r * hn);
            const float hold = h_s[b][hbase + m_loc];
            const float hnew = (1.f - z) * nn + z * hold;

            if (t + 1 < T_STEPS) {
                const uint32_t boff = (uint32_t)(((t + 1) & 1) * (DIM * 4));
                const uint32_t moff = (uint32_t)(((t + 1) & 1) * 8);
#pragma unroll
                for (int d = 0; d < NCC; ++d)
                    st_async_b32(rdata[d] + boff, hnew, rmbar[d] + moff);
            }

            g_ys[t * DIM + hbase + m_loc] = hnew;
            if (t + 1 < T_STEPS) {
                const float* p = g_xg + (t + 1) * G3 + hbase + m_loc;
                xr = p[0]; xz = p[DIM]; xn = p[2 * DIM];
            }
        }
        // ordering of buffer reuse is carried by the tx-barrier (every warp's
        // gate lanes contribute to it, and each lane's step-t reads precede its
        // step-t+1 shfl participation in program order).
    }

    cluster_arrive_rel();
    cluster_wait_acq();
}

// ================================================================================
// fp32 tiled GEMM, f32x2 inner loop + register double-buffering of global loads.
// BM=BN=128, BK=8, 256 threads, 8x8 micro-tile.
// ================================================================================
__global__ __launch_bounds__(256)
void gemm_kernel(const float* __restrict__ A, const float* __restrict__ B,
                 const float* __restrict__ bias, float* __restrict__ C,
                 int M, int N, int K, int reluA, int reluOut)
{
    constexpr int BM = 128, BN = 128, BK = 8;
    __shared__ __align__(16) float As[BK][BM];
    __shared__ __align__(16) float Bs[BK][BN];

    const int tid = threadIdx.x;
    const int bm = blockIdx.y * BM;
    const int bn = blockIdx.x * BN;
    const int tx = tid & 15;
    const int ty = tid >> 4;

    const int aRow = tid >> 1;
    const int aCol = (tid & 1) * 4;
    const int bRow = tid >> 5;
    const int bCol = (tid & 31) * 4;

    const float* Aptr = A + (size_t)(bm + aRow) * K + aCol;
    const float* Bptr = B + (size_t)bRow * N + bn + bCol;

    unsigned long long acc2[8][4];
#pragma unroll
    for (int i = 0; i < 8; ++i)
#pragma unroll
        for (int j = 0; j < 4; ++j) acc2[i][j] = 0ull;

    float4 av = *(const float4*)(Aptr);
    float4 bv = *(const float4*)(Bptr);

    for (int k0 = 0; k0 < K; k0 += BK) {
        if (reluA) {
            av.x = fmaxf(av.x, 0.f); av.y = fmaxf(av.y, 0.f);
            av.z = fmaxf(av.z, 0.f); av.w = fmaxf(av.w, 0.f);
        }
        As[aCol + 0][aRow] = av.x;
        As[aCol + 1][aRow] = av.y;
        As[aCol + 2][aRow] = av.z;
        As[aCol + 3][aRow] = av.w;
        *(float4*)&Bs[bRow][bCol] = bv;
        __syncthreads();

        // prefetch next tile's global data into registers (overlaps compute)
        if (k0 + BK < K) {
            av = *(const float4*)(Aptr + k0 + BK);
            bv = *(const float4*)(Bptr + (size_t)(k0 + BK) * N);
        }

#pragma unroll
        for (int k = 0; k < BK; ++k) {
            float a[8];
            *(float4*)(a)     = *(const float4*)&As[k][ty * 8];
            *(float4*)(a + 4) = *(const float4*)&As[k][ty * 8 + 4];
            unsigned long long b2[4];
            {
                const ulonglong2 p0 = *(const ulonglong2*)&Bs[k][tx * 8];
                const ulonglong2 p1 = *(const ulonglong2*)&Bs[k][tx * 8 + 4];
                b2[0] = p0.x; b2[1] = p0.y; b2[2] = p1.x; b2[3] = p1.y;
            }
#pragma unroll
            for (int i = 0; i < 8; ++i) {
                const unsigned long long ad = dup2(a[i]);
#pragma unroll
                for (int j = 0; j < 4; ++j) fma2(acc2[i][j], ad, b2[j]);
            }
        }
        __syncthreads();
    }

    float bias_r[8];
#pragma unroll
    for (int j = 0; j < 8; ++j) bias_r[j] = bias ? bias[bn + tx * 8 + j] : 0.f;

#pragma unroll
    for (int i = 0; i < 8; ++i) {
        const int row = bm + ty * 8 + i;
        float* cp = C + (size_t)row * N + bn + tx * 8;
        float o[8];
#pragma unroll
        for (int j = 0; j < 4; ++j) {
            float lo, hi;
            asm("mov.b64 {%0, %1}, %2;" : "=f"(lo), "=f"(hi) : "l"(acc2[i][j]));
            o[2 * j] = lo; o[2 * j + 1] = hi;
        }
#pragma unroll
        for (int j = 0; j < 8; ++j) {
            float v = o[j] + bias_r[j];
            o[j] = reluOut ? fmaxf(v, 0.f) : v;
        }
        *(float4*)cp       = *(float4*)(o);
        *(float4*)(cp + 4) = *(float4*)(o + 4);
    }
}

// ================================================================================
// Fused residual + LayerNorm (rows of 256): out = LN(base + delta)*g + b
// ================================================================================
__global__ __launch_bounds__(256)
void ln_kernel(const float* __restrict__ base, const float* __restrict__ delta,
               const float* __restrict__ g, const float* __restrict__ b,
               float* __restrict__ out)
{
    const int row  = blockIdx.x * 8 + (threadIdx.x >> 5);
    const int lane = threadIdx.x & 31;

    const float4* bp = (const float4*)(base  + (size_t)row * DIM);
    const float4* dp = (const float4*)(delta + (size_t)row * DIM);
    float4 x0 = bp[lane],      d0 = dp[lane];
    float4 x1 = bp[32 + lane], d1 = dp[32 + lane];
    float4 u0, u1;
    u0.x = x0.x + d0.x; u0.y = x0.y + d0.y; u0.z = x0.z + d0.z; u0.w = x0.w + d0.w;
    u1.x = x1.x + d1.x; u1.y = x1.y + d1.y; u1.z = x1.z + d1.z; u1.w = x1.w + d1.w;

    float s  = u0.x + u0.y + u0.z + u0.w + u1.x + u1.y + u1.z + u1.w;
    float ss = u0.x*u0.x + u0.y*u0.y + u0.z*u0.z + u0.w*u0.w
             + u1.x*u1.x + u1.y*u1.y + u1.z*u1.z + u1.w*u1.w;
#pragma unroll
    for (int o = 16; o > 0; o >>= 1) {
        s  += __shfl_xor_sync(0xffffffffu, s, o);
        ss += __shfl_xor_sync(0xffffffffu, ss, o);
    }
    const float mean = s * (1.f / DIM);
    const float var  = ss * (1.f / DIM) - mean * mean;
    const float rstd = rsqrtf(var + 1e-6f);

    const float4 gv0 = ((const float4*)g)[lane];
    const float4 gv1 = ((const float4*)g)[32 + lane];
    const float4 bv0 = ((const float4*)b)[lane];
    const float4 bv1 = ((const float4*)b)[32 + lane];

    float4 o0, o1;
    o0.x = (u0.x - mean) * rstd * gv0.x + bv0.x;
    o0.y = (u0.y - mean) * rstd * gv0.y + bv0.y;
    o0.z = (u0.z - mean) * rstd * gv0.z + bv0.z;
    o0.w = (u0.w - mean) * rstd * gv0.w + bv0.w;
    o1.x = (u1.x - mean) * rstd * gv1.x + bv1.x;
    o1.y = (u1.y - mean) * rstd * gv1.y + bv1.y;
    o1.z = (u1.z - mean) * rstd * gv1.z + bv1.z;
    o1.w = (u1.w - mean) * rstd * gv1.w + bv1.w;

    float4* op = (float4*)(out + (size_t)row * DIM);
    op[lane] = o0;
    op[32 + lane] = o1;
}

// ================================================================================
extern "C" void kernel_launch(void* const* d_in, const int* in_sizes, int n_in,
                              void* d_out, int out_size)
{
    (void)in_sizes; (void)n_in; (void)out_size;
    const float* xs  = (const float*)d_in[0];
    const float* h0  = (const float*)d_in[1];
    const float* Wi  = (const float*)d_in[2];
    const float* Wh  = (const float*)d_in[3];
    const float* bh  = (const float*)d_in[4];
    const float* Wg  = (const float*)d_in[5];
    const float* bg  = (const float*)d_in[6];
    const float* g1  = (const float*)d_in[7];
    const float* be1 = (const float*)d_in[8];
    const float* W1  = (const float*)d_in[9];
    const float* b1  = (const float*)d_in[10];
    const float* W2  = (const float*)d_in[11];
    const float* b2  = (const float*)d_in[12];
    const float* g2  = (const float*)d_in[13];
    const float* be2 = (const float*)d_in[14];
    float* out = (float*)d_out;

    float *xg, *ys, *t3, *y, *t1, *t6;
    cudaGetSymbolAddress((void**)&xg, g_xg);
    cudaGetSymbolAddress((void**)&ys, g_ys);
    cudaGetSymbolAddress((void**)&t3, g_t3);
    cudaGetSymbolAddress((void**)&y,  g_y);
    cudaGetSymbolAddress((void**)&t1, g_t1);
    cudaGetSymbolAddress((void**)&t6, g_t6);

    // 1) xg = xs @ Wi
    gemm_kernel<<<dim3(G3 / 128, T_STEPS / 128), 256>>>(xs, Wi, nullptr, xg,
                                                        T_STEPS, G3, DIM, 0, 0);

    // 2) sequential GRU scan -> ys. Prefer a 16-CTA cluster (non-portable on
    //    GB300); deterministically probe support each call, fall back to 8.
    {
        cudaLaunchAttribute cattr[1];
        cattr[0].id = cudaLaunchAttributeClusterDimension;
        cattr[0].val.clusterDim.x = 16;
        cattr[0].val.clusterDim.y = 1;
        cattr[0].val.clusterDim.z = 1;
        cudaLaunchConfig_t cfg = {};
        cfg.gridDim  = dim3(16, 1, 1);
        cfg.blockDim = dim3(128, 1, 1);
        cfg.dynamicSmemBytes = 0;
        cfg.stream = 0;
        cfg.attrs = cattr;
        cfg.numAttrs = 1;

        bool use16 = false;
        if (cudaFuncSetAttribute(scan_kernel<16>,
                                 cudaFuncAttributeNonPortableClusterSizeAllowed, 1)
            == cudaSuccess) {
            int nclus = 0;
            if (cudaOccupancyMaxActiveClusters(&nclus, scan_kernel<16>, &cfg)
                    == cudaSuccess && nclus >= 1)
                use16 = true;
        }
        (void)cudaGetLastError();   // clear any probe error

        if (use16) {
            cudaLaunchKernelEx(&cfg, scan_kernel<16>, Wh, bh, h0);
        } else {
            cattr[0].val.clusterDim.x = 8;
            cfg.gridDim  = dim3(8, 1, 1);
            cfg.blockDim = dim3(256, 1, 1);
            cudaLaunchKernelEx(&cfg, scan_kernel<8>, Wh, bh, h0);
        }
    }

    // 3) t3 = relu(ys) @ Wg + bg
    gemm_kernel<<<dim3(DIM / 128, T_STEPS / 128), 256>>>(ys, Wg, bg, t3,
                                                         T_STEPS, DIM, DIM, 1, 0);
    // 4) y = LN(xs + t3) * g1 + be1
    ln_kernel<<<T_STEPS / 8, 256>>>(xs, t3, g1, be1, y);
    // 5) t1 = relu(y @ W1 + b1)
    gemm_kernel<<<dim3(FFN_DIM / 128, T_STEPS / 128), 256>>>(y, W1, b1, t1,
                                                             T_STEPS, FFN_DIM, DIM, 0, 1);
    // 6) t6 = t1 @ W2 + b2
    gemm_kernel<<<dim3(DIM / 128, T_STEPS / 128), 256>>>(t1, W2, b2, t6,
                                                         T_STEPS, DIM, FFN_DIM, 0, 0);
    // 7) out = LN(y + t6) * g2 + be2
    ln_kernel<<<T_STEPS / 8, 256>>>(y, t6, g2, be2, out);
}